// round 16
// baseline (speedup 1.0000x reference)
#include <cuda_runtime.h>
#include <cuda_bf16.h>
#include <stdint.h>
#include <math.h>

#define BATCH 32
#define CH    512
#define NTOK  1024
#define NGRP  32
#define CPG   16

typedef __nv_bfloat16 bf16;
typedef unsigned int u32;

// ---------------- scratch (device globals) ----------------
__device__ bf16  g_h  [(size_t)BATCH * NTOK * CH];   // [b][t][c]
__device__ bf16  g_hT [(size_t)BATCH * CH * NTOK];   // [b][c][t]
__device__ bf16  g_G  [(size_t)BATCH * NTOK * CH];   // h . M
__device__ bf16  g_s  [(size_t)BATCH * NTOK * NTOK]; // scores
__device__ bf16  g_p  [(size_t)BATCH * NTOK * NTOK]; // probs
__device__ bf16  g_R  [(size_t)BATCH * NTOK * CH];   // P . h
__device__ bf16  g_wT [3 * CH * CH];                 // wqT|wkT|wvT
__device__ bf16  g_wp [CH * CH];                     // wp bf16
__device__ bf16  g_Mt [CH * CH];                     // Mt[c2][c1]=sum_o Wk[o][c2]Wq[o][c1]
__device__ bf16  g_Wpv[CH * CH];                     // Wpv[o][ci]=sum_c Wp[o][c]Wv[c][ci]
__device__ float g_u  [CH];                          // Wq^T bk
__device__ float g_v  [CH];                          // Wk^T bq
__device__ float g_pb [CH];                          // Wp bv + bp
__device__ float g_cc [1];                           // bq.bk
__device__ float g_sbm[(size_t)BATCH * NTOK];        // scale * (h.u)
__device__ float g_sbn[(size_t)BATCH * NTOK];        // scale * (h.v + cc)

// ---------------- weights: bf16 + transposes ----------------
__global__ void convw_kernel(const float* __restrict__ wq, const float* __restrict__ wk,
                             const float* __restrict__ wv, const float* __restrict__ wp) {
    int i = blockIdx.x * 256 + threadIdx.x;
    if (i < CH * CH) {
        int o = i / CH, c = i % CH;
        g_wT[c * CH + o]              = __float2bfloat16(wq[i]);   // wqT[c][o]
        g_wT[CH * CH + c * CH + o]    = __float2bfloat16(wk[i]);   // wkT[c][o]
        g_wT[2 * CH * CH + c * CH + o] = __float2bfloat16(wv[i]);  // wvT[c][o]
        g_wp[i] = __float2bfloat16(wp[i]);
    }
}

// ---------------- bias precompute (fp32, exact) ----------------
__global__ void prep_kernel(const float* __restrict__ wq, const float* __restrict__ wk,
                            const float* __restrict__ wp,
                            const float* __restrict__ bq, const float* __restrict__ bk,
                            const float* __restrict__ bv, const float* __restrict__ bp) {
    const int c = threadIdx.x;   // one block, 512 threads
    float su = 0.f, sv = 0.f, sp = 0.f;
    for (int o = 0; o < CH; o++) {
        su += wq[o * CH + c] * bk[o];
        sv += wk[o * CH + c] * bq[o];
        sp += wp[c * CH + o] * bv[o];   // row c of wp
    }
    g_u[c] = su;
    g_v[c] = sv;
    g_pb[c] = sp + bp[c];
    if (c == 0) {
        float cc = 0.f;
        for (int o = 0; o < CH; o++) cc += bq[o] * bk[o];
        g_cc[0] = cc;
    }
}

// ---------------- GroupNorm: single pass, writes h and hT ----------------
__global__ void __launch_bounds__(256)
gn_kernel(const float* __restrict__ x,
          const float* __restrict__ gw,
          const float* __restrict__ gb) {
    const int bg = blockIdx.x;
    const int b = bg / NGRP, g = bg % NGRP;
    const int n = CPG * NTOK;
    const size_t base = (size_t)bg * n;
    const int t = threadIdx.x;

    float v[4][CPG];
    float s = 0.f, ss = 0.f;
    #pragma unroll
    for (int j = 0; j < 4; j++) {
        const int tok = t + 256 * j;
        #pragma unroll
        for (int i = 0; i < CPG; i++) {
            float val = x[base + (size_t)i * NTOK + tok];
            v[j][i] = val; s += val; ss += val * val;
        }
    }
    __shared__ float rs[256], rq[256];
    rs[t] = s; rq[t] = ss;
    __syncthreads();
    for (int o = 128; o > 0; o >>= 1) {
        if (t < o) { rs[t] += rs[t + o]; rq[t] += rq[t + o]; }
        __syncthreads();
    }
    const float mean = rs[0] * (1.0f / n);
    const float var  = rq[0] * (1.0f / n) - mean * mean;
    const float rstd = rsqrtf(var + 1e-5f);

    float a[CPG], c[CPG];
    #pragma unroll
    for (int i = 0; i < CPG; i++) {
        a[i] = rstd * gw[g * CPG + i];
        c[i] = gb[g * CPG + i] - mean * a[i];
    }
    #pragma unroll
    for (int j = 0; j < 4; j++) {
        const int tok = t + 256 * j;
        bf16 buf[CPG];
        #pragma unroll
        for (int i = 0; i < CPG; i++)
            buf[i] = __float2bfloat16(v[j][i] * a[i] + c[i]);
        size_t ho = ((size_t)(b * NTOK + tok)) * CH + g * CPG;
        uint4* dst = reinterpret_cast<uint4*>(&g_h[ho]);
        const uint4* src = reinterpret_cast<const uint4*>(buf);
        dst[0] = src[0];
        dst[1] = src[1];
        // transposed copy (coalesced across threads per channel)
        #pragma unroll
        for (int i = 0; i < CPG; i++)
            g_hT[((size_t)b * CH + g * CPG + i) * NTOK + tok] = buf[i];
    }
}

// ---------------- per-token bias GEMV: sbm = scale*(h.u), sbn = scale*(h.v+cc)
__global__ void __launch_bounds__(256)
gemv_kernel(float scale) {
    const int warp = threadIdx.x >> 5, lane = threadIdx.x & 31;
    const size_t tokg = (size_t)blockIdx.x * 8 + warp;   // b*NTOK + t
    const bf16* hp = g_h + tokg * CH;
    float du = 0.f, dv = 0.f;
    #pragma unroll
    for (int i = 0; i < 2; i++) {
        uint4 raw = reinterpret_cast<const uint4*>(hp)[lane + 32 * i];
        const bf16* e = reinterpret_cast<const bf16*>(&raw);
        const int cb = (lane + 32 * i) * 8;
        #pragma unroll
        for (int j = 0; j < 8; j++) {
            float hv = __bfloat162float(e[j]);
            du += hv * g_u[cb + j];
            dv += hv * g_v[cb + j];
        }
    }
    #pragma unroll
    for (int o = 16; o > 0; o >>= 1) {
        du += __shfl_xor_sync(0xffffffffu, du, o);
        dv += __shfl_xor_sync(0xffffffffu, dv, o);
    }
    if (lane == 0) {
        g_sbm[tokg] = scale * du;
        g_sbn[tokg] = scale * (dv + g_cc[0]);
    }
}

// ---------------- epilogue store helpers ----------------
__device__ __forceinline__ void store2(float* p, float v0, float v1) {
    *reinterpret_cast<float2*>(p) = make_float2(v0, v1);
}
__device__ __forceinline__ void store2(bf16* p, float v0, float v1) {
    *reinterpret_cast<__nv_bfloat162*>(p) = __floats2bfloat162_rn(v0, v1);
}

// ---------------- bf16 TN GEMM: 128x128 tile, 128 thr, 64x64 warp tile ------
// C[m][n] = alpha*sum_k A[m][k]*B[n][k] (+bias_m[bz*sBm+m]) (+bias_n[bz*sBn+n]) (+resid)
#define BM 128
#define BN 128
#define BK 64
#define LDSW 72
#define NSTG 3
#define NTHR 128
#define GEMM_SMEM ((BM + BN) * LDSW * NSTG * 2)   // 110592 bytes

template<typename OutT, int LDA, int LDB>
__global__ void __launch_bounds__(NTHR, 2)
mma_gemm(const bf16* __restrict__ A, const bf16* __restrict__ B, OutT* __restrict__ C,
         int K, int N, long sA, long sB, long sC, float alpha,
         const float* __restrict__ bias_m, long sBm,
         const float* __restrict__ bias_n, long sBn,
         const float* __restrict__ resid, long sR) {
    extern __shared__ bf16 sm[];
    bf16* Asm = sm;
    bf16* Bsm = sm + NSTG * BM * LDSW;

    const int bz = blockIdx.z;
    const bf16* Ab = A + (size_t)bz * sA + (size_t)(blockIdx.y * BM) * LDA;
    const bf16* Bb = B + (size_t)bz * sB + (size_t)(blockIdx.x * BN) * LDB;

    const int t = threadIdx.x;
    const int lane = t & 31, w = t >> 5;
    const int wm = (w >> 1) * 64, wn = (w & 1) * 64;

    const int lr = t >> 3;
    const int lc = (t & 7) * 8;

    const int a_row = wm + (lane & 15);
    const int a_col = (lane >> 4) * 8;
    const int b_row = wn + (lane & 7) + ((lane >> 4) << 3);
    const int b_col = ((lane >> 3) & 1) * 8;

    float acc[4][8][4] = {};

    auto issue = [&](int j) {
        const int st = j % NSTG;
        const int k0 = j * BK;
        #pragma unroll
        for (int i = 0; i < 8; i++) {
            int r = lr + i * 16;
            u32 da = (u32)__cvta_generic_to_shared(&Asm[st * BM * LDSW + r * LDSW + lc]);
            const bf16* ga = Ab + (size_t)r * LDA + k0 + lc;
            asm volatile("cp.async.cg.shared.global [%0], [%1], 16;\n" :: "r"(da), "l"(ga));
            u32 db = (u32)__cvta_generic_to_shared(&Bsm[st * BN * LDSW + r * LDSW + lc]);
            const bf16* gbp = Bb + (size_t)r * LDB + k0 + lc;
            asm volatile("cp.async.cg.shared.global [%0], [%1], 16;\n" :: "r"(db), "l"(gbp));
        }
        asm volatile("cp.async.commit_group;\n");
    };

    const int KT = K / BK;
    issue(0);
    if (1 < KT) issue(1);

    for (int kt = 0; kt < KT; kt++) {
        if (kt + 1 < KT) {
            asm volatile("cp.async.wait_group 1;\n");
        } else {
            asm volatile("cp.async.wait_group 0;\n");
        }
        __syncthreads();
        const int st = kt % NSTG;
        const bf16* as = Asm + st * BM * LDSW;
        const bf16* bs = Bsm + st * BN * LDSW;

        u32 afrag[2][4][4], bfrag[2][8][2];

        auto load_frags = [&](int ks, int buf) {
            const int colA = ks * 16 + a_col;
            const int colB = ks * 16 + b_col;
            #pragma unroll
            for (int mt = 0; mt < 4; mt++) {
                u32 addr = (u32)__cvta_generic_to_shared(&as[(a_row + mt * 16) * LDSW + colA]);
                asm volatile("ldmatrix.sync.aligned.m8n8.x4.shared.b16 {%0,%1,%2,%3}, [%4];\n"
                    : "=r"(afrag[buf][mt][0]), "=r"(afrag[buf][mt][1]),
                      "=r"(afrag[buf][mt][2]), "=r"(afrag[buf][mt][3])
                    : "r"(addr));
            }
            #pragma unroll
            for (int np = 0; np < 4; np++) {
                u32 addr = (u32)__cvta_generic_to_shared(&bs[(b_row + np * 16) * LDSW + colB]);
                u32 bt0, bt1, bt2, bt3;
                asm volatile("ldmatrix.sync.aligned.m8n8.x4.shared.b16 {%0,%1,%2,%3}, [%4];\n"
                    : "=r"(bt0), "=r"(bt1), "=r"(bt2), "=r"(bt3) : "r"(addr));
                bfrag[buf][np * 2][0]     = bt0;
                bfrag[buf][np * 2][1]     = bt1;
                bfrag[buf][np * 2 + 1][0] = bt2;
                bfrag[buf][np * 2 + 1][1] = bt3;
            }
        };

        load_frags(0, 0);
        #pragma unroll
        for (int ks = 0; ks < 4; ks++) {
            const int cur = ks & 1;
            if (ks < 3) load_frags(ks + 1, cur ^ 1);
            #pragma unroll
            for (int mt = 0; mt < 4; mt++)
                #pragma unroll
                for (int nt = 0; nt < 8; nt++)
                    asm volatile(
                        "mma.sync.aligned.m16n8k16.row.col.f32.bf16.bf16.f32 "
                        "{%0,%1,%2,%3}, {%4,%5,%6,%7}, {%8,%9}, {%0,%1,%2,%3};\n"
                        : "+f"(acc[mt][nt][0]), "+f"(acc[mt][nt][1]),
                          "+f"(acc[mt][nt][2]), "+f"(acc[mt][nt][3])
                        : "r"(afrag[cur][mt][0]), "r"(afrag[cur][mt][1]),
                          "r"(afrag[cur][mt][2]), "r"(afrag[cur][mt][3]),
                          "r"(bfrag[cur][nt][0]), "r"(bfrag[cur][nt][1]));
        }
        if (kt + 2 < KT) issue(kt + 2);
    }

    // --- epilogue ---
    const int m0 = blockIdx.y * BM + wm, n0 = blockIdx.x * BN + wn;
    OutT* Cb = C + (size_t)bz * sC;
    const float* Bm = bias_m ? bias_m + (size_t)bz * sBm : nullptr;
    const float* Bn = bias_n ? bias_n + (size_t)bz * sBn : nullptr;
    const float* Rb = resid ? resid + (size_t)bz * sR : nullptr;
    #pragma unroll
    for (int mt = 0; mt < 4; mt++) {
        #pragma unroll
        for (int hh = 0; hh < 2; hh++) {
            int m = m0 + mt * 16 + (lane >> 2) + hh * 8;
            float bm = Bm ? Bm[m] : 0.f;
            #pragma unroll
            for (int nt = 0; nt < 8; nt++) {
                int n = n0 + nt * 8 + (lane & 3) * 2;
                float v0 = alpha * acc[mt][nt][hh * 2 + 0] + bm;
                float v1 = alpha * acc[mt][nt][hh * 2 + 1] + bm;
                if (Bn) { v0 += Bn[n]; v1 += Bn[n + 1]; }
                size_t idx = (size_t)m * N + n;
                if (Rb) { v0 += Rb[idx]; v1 += Rb[idx + 1]; }
                store2(&Cb[idx], v0, v1);
            }
        }
    }
}

// ---------------- row softmax: one warp per row, bf16 in/out ----------------
__global__ void __launch_bounds__(256)
softmax_kernel(const bf16* __restrict__ s, bf16* __restrict__ p) {
    const int warp = threadIdx.x >> 5, lane = threadIdx.x & 31;
    const size_t row = (size_t)blockIdx.x * 8 + warp;
    const bf16* sp = s + row * NTOK;
    bf16* pp = p + row * NTOK;

    uint4 raw[4];
    #pragma unroll
    for (int i = 0; i < 4; i++)
        raw[i] = reinterpret_cast<const uint4*>(sp)[lane + 32 * i];

    float v[32];
    #pragma unroll
    for (int i = 0; i < 4; i++) {
        const bf16* e = reinterpret_cast<const bf16*>(&raw[i]);
        #pragma unroll
        for (int j = 0; j < 8; j++) v[i * 8 + j] = __bfloat162float(e[j]);
    }

    float mx = -1e30f;
    #pragma unroll
    for (int i = 0; i < 32; i++) mx = fmaxf(mx, v[i]);
    #pragma unroll
    for (int o = 16; o > 0; o >>= 1)
        mx = fmaxf(mx, __shfl_xor_sync(0xffffffffu, mx, o));

    float sum = 0.f;
    #pragma unroll
    for (int i = 0; i < 32; i++) { v[i] = __expf(v[i] - mx); sum += v[i]; }
    #pragma unroll
    for (int o = 16; o > 0; o >>= 1)
        sum += __shfl_xor_sync(0xffffffffu, sum, o);

    const float inv = __frcp_rn(sum);
    uint4 outw[4];
    #pragma unroll
    for (int i = 0; i < 4; i++) {
        bf16* e = reinterpret_cast<bf16*>(&outw[i]);
        #pragma unroll
        for (int j = 0; j < 8; j += 2) {
            __nv_bfloat162 pr = __floats2bfloat162_rn(v[i * 8 + j] * inv, v[i * 8 + j + 1] * inv);
            *reinterpret_cast<__nv_bfloat162*>(&e[j]) = pr;
        }
        reinterpret_cast<uint4*>(pp)[lane + 32 * i] = outw[i];
    }
}

extern "C" void kernel_launch(void* const* d_in, const int* in_sizes, int n_in,
                              void* d_out, int out_size) {
    (void)in_sizes; (void)n_in; (void)out_size;
    const float* x  = (const float*)d_in[0];
    const float* gw = (const float*)d_in[1];
    const float* gb = (const float*)d_in[2];
    const float* wq = (const float*)d_in[3];
    const float* bq = (const float*)d_in[4];
    const float* wk = (const float*)d_in[5];
    const float* bk = (const float*)d_in[6];
    const float* wv = (const float*)d_in[7];
    const float* bv = (const float*)d_in[8];
    const float* wp = (const float*)d_in[9];
    const float* bp = (const float*)d_in[10];
    float* out = (float*)d_out;

    bf16 *h, *hT, *G, *s, *p, *R, *wT, *wpb, *Mt, *Wpv;
    float *sbm, *sbn, *pb;
    cudaGetSymbolAddress((void**)&h,   g_h);
    cudaGetSymbolAddress((void**)&hT,  g_hT);
    cudaGetSymbolAddress((void**)&G,   g_G);
    cudaGetSymbolAddress((void**)&s,   g_s);
    cudaGetSymbolAddress((void**)&p,   g_p);
    cudaGetSymbolAddress((void**)&R,   g_R);
    cudaGetSymbolAddress((void**)&wT,  g_wT);
    cudaGetSymbolAddress((void**)&wpb, g_wp);
    cudaGetSymbolAddress((void**)&Mt,  g_Mt);
    cudaGetSymbolAddress((void**)&Wpv, g_Wpv);
    cudaGetSymbolAddress((void**)&sbm, g_sbm);
    cudaGetSymbolAddress((void**)&sbn, g_sbn);
    cudaGetSymbolAddress((void**)&pb,  g_pb);

    cudaFuncSetAttribute((const void*)mma_gemm<bf16, CH, CH>,
                         cudaFuncAttributeMaxDynamicSharedMemorySize, GEMM_SMEM);
    cudaFuncSetAttribute((const void*)mma_gemm<bf16, NTOK, NTOK>,
                         cudaFuncAttributeMaxDynamicSharedMemorySize, GEMM_SMEM);
    cudaFuncSetAttribute((const void*)mma_gemm<float, CH, CH>,
                         cudaFuncAttributeMaxDynamicSharedMemorySize, GEMM_SMEM);

    const long NC = (long)NTOK * CH;
    const long SS = (long)NTOK * NTOK;
    const float scale = 1.0f / sqrtf((float)CH);

    convw_kernel<<<(CH * CH + 255) / 256, 256>>>(wq, wk, wv, wp);
    prep_kernel<<<1, CH>>>(wq, wk, wp, bq, bk, bv, bp);
    gn_kernel<<<BATCH * NGRP, 256>>>(x, gw, gb);

    // Mt[c2][c1] = sum_o wkT[c2][o] wqT[c1][o]
    dim3 gM(CH / BN, CH / BM, 1);             // (4,4,1)
    mma_gemm<bf16, CH, CH><<<gM, NTHR, GEMM_SMEM>>>(
        wT + CH * CH, wT, Mt, CH, CH, 0, 0, 0, 1.f,
        nullptr, 0, nullptr, 0, nullptr, 0);

    // Wpv[o][ci] = sum_c wp[o][c] wvT[ci][c]
    mma_gemm<bf16, CH, CH><<<gM, NTHR, GEMM_SMEM>>>(
        wpb, wT + 2 * CH * CH, Wpv, CH, CH, 0, 0, 0, 1.f,
        nullptr, 0, nullptr, 0, nullptr, 0);

    // per-token score biases
    gemv_kernel<<<BATCH * NTOK / 8, 256>>>(scale);

    // G[t][c2] = sum_c1 h[t][c1] Mt[c2][c1]
    dim3 gG(CH / BN, NTOK / BM, BATCH);       // (4,8,32)
    mma_gemm<bf16, CH, CH><<<gG, NTHR, GEMM_SMEM>>>(
        h, Mt, G, CH, CH, NC, 0, NC, 1.f,
        nullptr, 0, nullptr, 0, nullptr, 0);

    // S[i][j] = scale*sum_c G[i][c] h[j][c] + sbm[i] + sbn[j]
    dim3 gS(NTOK / BN, NTOK / BM, BATCH);     // (8,8,32)
    mma_gemm<bf16, CH, CH><<<gS, NTHR, GEMM_SMEM>>>(
        G, h, s, CH, NTOK, NC, NC, SS, scale,
        sbm, NTOK, sbn, NTOK, nullptr, 0);

    softmax_kernel<<<BATCH * NTOK / 8, 256>>>(s, p);

    // R[t][ci] = sum_j P[t][j] hT[ci][j]
    dim3 gR(CH / BN, NTOK / BM, BATCH);       // (4,8,32)
    mma_gemm<bf16, NTOK, NTOK><<<gR, NTHR, GEMM_SMEM>>>(
        p, hT, R, NTOK, CH, SS, NC, NC, 1.f,
        nullptr, 0, nullptr, 0, nullptr, 0);

    // out[o][t] = x + sum_ci Wpv[o][ci] R[t][ci] + pb[o]
    dim3 gP(NTOK / BN, CH / BM, BATCH);       // (8,4,32)
    mma_gemm<float, CH, CH><<<gP, NTHR, GEMM_SMEM>>>(
        Wpv, R, out, CH, NTOK, 0, NC, NC, 1.f,
        pb, 0, nullptr, 0, x, NC);
}

// round 17
// speedup vs baseline: 1.1484x; 1.1484x over previous
#include <cuda_runtime.h>
#include <cuda_bf16.h>
#include <stdint.h>
#include <math.h>

#define BATCH 32
#define CH    512
#define NTOK  1024
#define NGRP  32
#define CPG   16

typedef __nv_bfloat16 bf16;
typedef unsigned int u32;

// ---------------- scratch (device globals) ----------------
__device__ bf16  g_h  [(size_t)BATCH * NTOK * CH];   // [b][t][c]
__device__ bf16  g_hT [(size_t)BATCH * CH * NTOK];   // [b][c][t]
__device__ bf16  g_G  [(size_t)BATCH * NTOK * CH];   // h.M (+v)
__device__ bf16  g_s  [(size_t)BATCH * NTOK * NTOK]; // scores
__device__ bf16  g_p  [(size_t)BATCH * NTOK * NTOK]; // probs
__device__ bf16  g_R  [(size_t)BATCH * NTOK * CH];   // P.h
__device__ bf16  g_wT [4 * CH * CH];                 // wqT|wkT|wp|wvT
__device__ bf16  g_MW [2 * CH * CH];                 // Mt | Wpv
__device__ float g_v  [CH];                          // Wk^T bq
__device__ float g_pb [CH];                          // Wp bv + bp

// ---------------- weights: tiled transpose to bf16 ----------------
// z=0: wq->slot0 (T), z=1: wk->slot1 (T), z=2: wv->slot3 (T), z=3: wp->slot2 (copy)
__global__ void __launch_bounds__(256)
convw_kernel(const float* __restrict__ wq, const float* __restrict__ wk,
             const float* __restrict__ wv, const float* __restrict__ wp) {
    __shared__ float tile[32][33];
    const int zi = blockIdx.z;
    const float* src = (zi == 0) ? wq : (zi == 1) ? wk : (zi == 2) ? wv : wp;
    const int slot = (zi == 0) ? 0 : (zi == 1) ? 1 : (zi == 2) ? 3 : 2;
    bf16* dst = g_wT + (size_t)slot * CH * CH;
    const int bx = blockIdx.x * 32, by = blockIdx.y * 32;
    const int tx = threadIdx.x & 31, ty0 = threadIdx.x >> 5;  // 32x8

    if (zi < 3) {
        #pragma unroll
        for (int i = 0; i < 4; i++) {
            int ty = ty0 + i * 8;
            tile[ty][tx] = src[(size_t)(by + ty) * CH + bx + tx];
        }
        __syncthreads();
        #pragma unroll
        for (int i = 0; i < 4; i++) {
            int ty = ty0 + i * 8;
            dst[(size_t)(bx + ty) * CH + by + tx] = __float2bfloat16(tile[tx][ty]);
        }
    } else {
        #pragma unroll
        for (int i = 0; i < 4; i++) {
            int ty = ty0 + i * 8;
            dst[(size_t)(by + ty) * CH + bx + tx] =
                __float2bfloat16(src[(size_t)(by + ty) * CH + bx + tx]);
        }
    }
}

// ---------------- bias precompute (fp32, exact) ----------------
__global__ void prep_kernel(const float* __restrict__ wk, const float* __restrict__ wp,
                            const float* __restrict__ bq, const float* __restrict__ bv,
                            const float* __restrict__ bp) {
    const int c = threadIdx.x;   // one block, 512 threads
    float sv = 0.f, sp = 0.f;
    for (int o = 0; o < CH; o++) {
        sv += wk[o * CH + c] * bq[o];
        sp += wp[c * CH + o] * bv[o];
    }
    g_v[c]  = sv;
    g_pb[c] = sp + bp[c];
}

// ---------------- GroupNorm: single pass, writes h and hT ----------------
__global__ void __launch_bounds__(256)
gn_kernel(const float* __restrict__ x,
          const float* __restrict__ gw,
          const float* __restrict__ gb) {
    const int bg = blockIdx.x;
    const int b = bg / NGRP, g = bg % NGRP;
    const int n = CPG * NTOK;
    const size_t base = (size_t)bg * n;
    const int t = threadIdx.x;

    float v[4][CPG];
    float s = 0.f, ss = 0.f;
    #pragma unroll
    for (int j = 0; j < 4; j++) {
        const int tok = t + 256 * j;
        #pragma unroll
        for (int i = 0; i < CPG; i++) {
            float val = x[base + (size_t)i * NTOK + tok];
            v[j][i] = val; s += val; ss += val * val;
        }
    }
    __shared__ float rs[256], rq[256];
    rs[t] = s; rq[t] = ss;
    __syncthreads();
    for (int o = 128; o > 0; o >>= 1) {
        if (t < o) { rs[t] += rs[t + o]; rq[t] += rq[t + o]; }
        __syncthreads();
    }
    const float mean = rs[0] * (1.0f / n);
    const float var  = rq[0] * (1.0f / n) - mean * mean;
    const float rstd = rsqrtf(var + 1e-5f);

    float a[CPG], c[CPG];
    #pragma unroll
    for (int i = 0; i < CPG; i++) {
        a[i] = rstd * gw[g * CPG + i];
        c[i] = gb[g * CPG + i] - mean * a[i];
    }
    #pragma unroll
    for (int j = 0; j < 4; j++) {
        const int tok = t + 256 * j;
        bf16 buf[CPG];
        #pragma unroll
        for (int i = 0; i < CPG; i++)
            buf[i] = __float2bfloat16(v[j][i] * a[i] + c[i]);
        size_t ho = ((size_t)(b * NTOK + tok)) * CH + g * CPG;
        uint4* dst = reinterpret_cast<uint4*>(&g_h[ho]);
        const uint4* src = reinterpret_cast<const uint4*>(buf);
        dst[0] = src[0];
        dst[1] = src[1];
        #pragma unroll
        for (int i = 0; i < CPG; i++)
            g_hT[((size_t)b * CH + g * CPG + i) * NTOK + tok] = buf[i];
    }
}

// ---------------- epilogue store helpers ----------------
__device__ __forceinline__ void store2(float* p, float v0, float v1) {
    *reinterpret_cast<float2*>(p) = make_float2(v0, v1);
}
__device__ __forceinline__ void store2(bf16* p, float v0, float v1) {
    *reinterpret_cast<__nv_bfloat162*>(p) = __floats2bfloat162_rn(v0, v1);
}

// ---------------- bf16 TN GEMM: 128x128 tile, 128 thr, 64x64 warp tile ------
// C[m][n] = alpha*sum_k A[m][k]*B[n][k] (+bias_m[m]) (+bias_n[n]) (+resid)
// (signature identical to R15's proven kernel)
#define BM 128
#define BN 128
#define BK 64
#define LDSW 72
#define NSTG 3
#define NTHR 128
#define GEMM_SMEM ((BM + BN) * LDSW * NSTG * 2)   // 110592 bytes

template<typename OutT, int LDA, int LDB>
__global__ void __launch_bounds__(NTHR, 2)
mma_gemm(const bf16* __restrict__ A, const bf16* __restrict__ B, OutT* __restrict__ C,
         int K, int N, long sA, long sB, long sC,
         float alpha, const float* __restrict__ bias_m, const float* __restrict__ bias_n,
         const float* __restrict__ resid, long sR) {
    extern __shared__ bf16 sm[];
    bf16* Asm = sm;
    bf16* Bsm = sm + NSTG * BM * LDSW;

    const int bz = blockIdx.z;
    const bf16* Ab = A + (size_t)bz * sA + (size_t)(blockIdx.y * BM) * LDA;
    const bf16* Bb = B + (size_t)bz * sB + (size_t)(blockIdx.x * BN) * LDB;

    const int t = threadIdx.x;
    const int lane = t & 31, w = t >> 5;
    const int wm = (w >> 1) * 64, wn = (w & 1) * 64;

    const int lr = t >> 3;
    const int lc = (t & 7) * 8;

    const int a_row = wm + (lane & 15);
    const int a_col = (lane >> 4) * 8;
    const int b_row = wn + (lane & 7) + ((lane >> 4) << 3);
    const int b_col = ((lane >> 3) & 1) * 8;

    float acc[4][8][4] = {};

    auto issue = [&](int j) {
        const int st = j % NSTG;
        const int k0 = j * BK;
        #pragma unroll
        for (int i = 0; i < 8; i++) {
            int r = lr + i * 16;
            u32 da = (u32)__cvta_generic_to_shared(&Asm[st * BM * LDSW + r * LDSW + lc]);
            const bf16* ga = Ab + (size_t)r * LDA + k0 + lc;
            asm volatile("cp.async.cg.shared.global [%0], [%1], 16;\n" :: "r"(da), "l"(ga));
            u32 db = (u32)__cvta_generic_to_shared(&Bsm[st * BN * LDSW + r * LDSW + lc]);
            const bf16* gbp = Bb + (size_t)r * LDB + k0 + lc;
            asm volatile("cp.async.cg.shared.global [%0], [%1], 16;\n" :: "r"(db), "l"(gbp));
        }
        asm volatile("cp.async.commit_group;\n");
    };

    const int KT = K / BK;
    issue(0);
    if (1 < KT) issue(1);

    for (int kt = 0; kt < KT; kt++) {
        if (kt + 1 < KT) {
            asm volatile("cp.async.wait_group 1;\n");
        } else {
            asm volatile("cp.async.wait_group 0;\n");
        }
        __syncthreads();
        const int st = kt % NSTG;
        const bf16* as = Asm + st * BM * LDSW;
        const bf16* bs = Bsm + st * BN * LDSW;

        u32 afrag[2][4][4], bfrag[2][8][2];

        auto load_frags = [&](int ks, int buf) {
            const int colA = ks * 16 + a_col;
            const int colB = ks * 16 + b_col;
            #pragma unroll
            for (int mt = 0; mt < 4; mt++) {
                u32 addr = (u32)__cvta_generic_to_shared(&as[(a_row + mt * 16) * LDSW + colA]);
                asm volatile("ldmatrix.sync.aligned.m8n8.x4.shared.b16 {%0,%1,%2,%3}, [%4];\n"
                    : "=r"(afrag[buf][mt][0]), "=r"(afrag[buf][mt][1]),
                      "=r"(afrag[buf][mt][2]), "=r"(afrag[buf][mt][3])
                    : "r"(addr));
            }
            #pragma unroll
            for (int np = 0; np < 4; np++) {
                u32 addr = (u32)__cvta_generic_to_shared(&bs[(b_row + np * 16) * LDSW + colB]);
                u32 bt0, bt1, bt2, bt3;
                asm volatile("ldmatrix.sync.aligned.m8n8.x4.shared.b16 {%0,%1,%2,%3}, [%4];\n"
                    : "=r"(bt0), "=r"(bt1), "=r"(bt2), "=r"(bt3) : "r"(addr));
                bfrag[buf][np * 2][0]     = bt0;
                bfrag[buf][np * 2][1]     = bt1;
                bfrag[buf][np * 2 + 1][0] = bt2;
                bfrag[buf][np * 2 + 1][1] = bt3;
            }
        };

        load_frags(0, 0);
        #pragma unroll
        for (int ks = 0; ks < 4; ks++) {
            const int cur = ks & 1;
            if (ks < 3) load_frags(ks + 1, cur ^ 1);
            #pragma unroll
            for (int mt = 0; mt < 4; mt++)
                #pragma unroll
                for (int nt = 0; nt < 8; nt++)
                    asm volatile(
                        "mma.sync.aligned.m16n8k16.row.col.f32.bf16.bf16.f32 "
                        "{%0,%1,%2,%3}, {%4,%5,%6,%7}, {%8,%9}, {%0,%1,%2,%3};\n"
                        : "+f"(acc[mt][nt][0]), "+f"(acc[mt][nt][1]),
                          "+f"(acc[mt][nt][2]), "+f"(acc[mt][nt][3])
                        : "r"(afrag[cur][mt][0]), "r"(afrag[cur][mt][1]),
                          "r"(afrag[cur][mt][2]), "r"(afrag[cur][mt][3]),
                          "r"(bfrag[cur][nt][0]), "r"(bfrag[cur][nt][1]));
        }
        if (kt + 2 < KT) issue(kt + 2);
    }

    // --- epilogue ---
    const int m0 = blockIdx.y * BM + wm, n0 = blockIdx.x * BN + wn;
    OutT* Cb = C + (size_t)bz * sC;
    const float* Rb = resid ? resid + (size_t)bz * sR : nullptr;
    #pragma unroll
    for (int mt = 0; mt < 4; mt++) {
        #pragma unroll
        for (int hh = 0; hh < 2; hh++) {
            int m = m0 + mt * 16 + (lane >> 2) + hh * 8;
            float bm = bias_m ? bias_m[m] : 0.f;
            #pragma unroll
            for (int nt = 0; nt < 8; nt++) {
                int n = n0 + nt * 8 + (lane & 3) * 2;
                float v0 = alpha * acc[mt][nt][hh * 2 + 0] + bm;
                float v1 = alpha * acc[mt][nt][hh * 2 + 1] + bm;
                if (bias_n) { v0 += bias_n[n]; v1 += bias_n[n + 1]; }
                size_t idx = (size_t)m * N + n;
                if (Rb) { v0 += Rb[idx]; v1 += Rb[idx + 1]; }
                store2(&Cb[idx], v0, v1);
            }
        }
    }
}

// ---------------- row softmax: one warp per row, bf16 in/out ----------------
__global__ void __launch_bounds__(256)
softmax_kernel(const bf16* __restrict__ s, bf16* __restrict__ p) {
    const int warp = threadIdx.x >> 5, lane = threadIdx.x & 31;
    const size_t row = (size_t)blockIdx.x * 8 + warp;
    const bf16* sp = s + row * NTOK;
    bf16* pp = p + row * NTOK;

    uint4 raw[4];
    #pragma unroll
    for (int i = 0; i < 4; i++)
        raw[i] = reinterpret_cast<const uint4*>(sp)[lane + 32 * i];

    float v[32];
    #pragma unroll
    for (int i = 0; i < 4; i++) {
        const bf16* e = reinterpret_cast<const bf16*>(&raw[i]);
        #pragma unroll
        for (int j = 0; j < 8; j++) v[i * 8 + j] = __bfloat162float(e[j]);
    }

    float mx = -1e30f;
    #pragma unroll
    for (int i = 0; i < 32; i++) mx = fmaxf(mx, v[i]);
    #pragma unroll
    for (int o = 16; o > 0; o >>= 1)
        mx = fmaxf(mx, __shfl_xor_sync(0xffffffffu, mx, o));

    float sum = 0.f;
    #pragma unroll
    for (int i = 0; i < 32; i++) { v[i] = __expf(v[i] - mx); sum += v[i]; }
    #pragma unroll
    for (int o = 16; o > 0; o >>= 1)
        sum += __shfl_xor_sync(0xffffffffu, sum, o);

    const float inv = __frcp_rn(sum);
    uint4 outw[4];
    #pragma unroll
    for (int i = 0; i < 4; i++) {
        bf16* e = reinterpret_cast<bf16*>(&outw[i]);
        #pragma unroll
        for (int j = 0; j < 8; j += 2) {
            __nv_bfloat162 pr = __floats2bfloat162_rn(v[i * 8 + j] * inv, v[i * 8 + j + 1] * inv);
            *reinterpret_cast<__nv_bfloat162*>(&e[j]) = pr;
        }
        reinterpret_cast<uint4*>(pp)[lane + 32 * i] = outw[i];
    }
}

extern "C" void kernel_launch(void* const* d_in, const int* in_sizes, int n_in,
                              void* d_out, int out_size) {
    (void)in_sizes; (void)n_in; (void)out_size;
    const float* x  = (const float*)d_in[0];
    const float* gw = (const float*)d_in[1];
    const float* gb = (const float*)d_in[2];
    const float* wq = (const float*)d_in[3];
    const float* bq = (const float*)d_in[4];
    const float* wk = (const float*)d_in[5];
    const float* bk = (const float*)d_in[6];
    const float* wv = (const float*)d_in[7];
    const float* bv = (const float*)d_in[8];
    const float* wp = (const float*)d_in[9];
    const float* bp = (const float*)d_in[10];
    float* out = (float*)d_out;
    (void)bk;

    bf16 *h, *hT, *G, *s, *p, *R, *wT, *MW;
    float *v, *pb;
    cudaGetSymbolAddress((void**)&h,  g_h);
    cudaGetSymbolAddress((void**)&hT, g_hT);
    cudaGetSymbolAddress((void**)&G,  g_G);
    cudaGetSymbolAddress((void**)&s,  g_s);
    cudaGetSymbolAddress((void**)&p,  g_p);
    cudaGetSymbolAddress((void**)&R,  g_R);
    cudaGetSymbolAddress((void**)&wT, g_wT);
    cudaGetSymbolAddress((void**)&MW, g_MW);
    cudaGetSymbolAddress((void**)&v,  g_v);
    cudaGetSymbolAddress((void**)&pb, g_pb);

    cudaFuncSetAttribute((const void*)mma_gemm<bf16, CH, CH>,
                         cudaFuncAttributeMaxDynamicSharedMemorySize, GEMM_SMEM);
    cudaFuncSetAttribute((const void*)mma_gemm<bf16, NTOK, NTOK>,
                         cudaFuncAttributeMaxDynamicSharedMemorySize, GEMM_SMEM);
    cudaFuncSetAttribute((const void*)mma_gemm<float, CH, CH>,
                         cudaFuncAttributeMaxDynamicSharedMemorySize, GEMM_SMEM);

    const long NC  = (long)NTOK * CH;
    const long SS  = (long)NTOK * NTOK;
    const long CC  = (long)CH * CH;
    const float scale = 1.0f / sqrtf((float)CH);

    // weights: wqT | wkT | wp | wvT
    dim3 gW(16, 16, 4);
    convw_kernel<<<gW, 256>>>(wq, wk, wv, wp);
    prep_kernel<<<1, CH>>>(wk, wp, bq, bv, bp);
    gn_kernel<<<BATCH * NGRP, 256>>>(x, gw, gb);

    // batched: bz=0 Mt[c2][c1]=sum_o wkT[c2][o] wqT[c1][o]
    //          bz=1 Wpv[o][ci]=sum_c wp[o][c] wvT[ci][c]
    dim3 gM(CH / BN, CH / BM, 2);             // (4,4,2)
    mma_gemm<bf16, CH, CH><<<gM, NTHR, GEMM_SMEM>>>(
        wT + CC, wT, MW, CH, CH, CC, 3 * CC, CC,
        1.f, nullptr, nullptr, nullptr, 0);

    // G[t][c2] = sum_c1 h[t][c1] Mt[c2][c1] + v[c2]
    dim3 gG(CH / BN, NTOK / BM, BATCH);       // (4,8,32)
    mma_gemm<bf16, CH, CH><<<gG, NTHR, GEMM_SMEM>>>(
        h, MW, G, CH, CH, NC, 0, NC,
        1.f, nullptr, v, nullptr, 0);

    // S[i][j] = scale * sum_c G[i][c] h[j][c]
    dim3 gS(NTOK / BN, NTOK / BM, BATCH);     // (8,8,32)
    mma_gemm<bf16, CH, CH><<<gS, NTHR, GEMM_SMEM>>>(
        G, h, s, CH, NTOK, NC, NC, SS,
        scale, nullptr, nullptr, nullptr, 0);

    softmax_kernel<<<BATCH * NTOK / 8, 256>>>(s, p);

    // R[t][ci] = sum_j P[t][j] hT[ci][j]
    dim3 gR(CH / BN, NTOK / BM, BATCH);       // (4,8,32)
    mma_gemm<bf16, NTOK, NTOK><<<gR, NTHR, GEMM_SMEM>>>(
        p, hT, R, NTOK, CH, SS, NC, NC,
        1.f, nullptr, nullptr, nullptr, 0);

    // out[o][t] = x + sum_ci Wpv[o][ci] R[t][ci] + pb[o]
    dim3 gP(NTOK / BN, CH / BM, BATCH);       // (8,4,32)
    mma_gemm<float, CH, CH><<<gP, NTHR, GEMM_SMEM>>>(
        MW + CC, R, out, CH, NTOK, 0, NC, NC,
        1.f, pb, nullptr, x, NC);
}